// round 9
// baseline (speedup 1.0000x reference)
#include <cuda_runtime.h>
#include <cuda_bf16.h>
#include <cstdint>

#define N_NODES 50000
#define N_EDGES 600000
#define NB      64
#define D       128      // F == H == U
#define NLAYERS 4

#define EPAD 132   // padded row stride for 128-wide smem tiles (node/global)
#define HPAD 36    // padded row stride for 32-wide K chunks (node)

#define LDA 136                      // bf16 row stride for mma tiles (272B, 16B-aligned)
#define WTILE_BYTES (128 * LDA * 2)  // 34816 bytes per 128x128 bf16 tile

// ===========================================================================
// Scratch (no allocations allowed -> __device__ globals)
// ===========================================================================
__device__ float g_x[2][N_NODES * D];
__device__ float g_u[2][NB * D];
__device__ float g_agg[N_NODES * D];
__device__ float g_cnt[N_NODES];
__device__ float g_xsum[NB * D];
__device__ float g_bcnt[NB];
// transposed/split bf16 weight tiles [n][k], padded LDA: [layer][w1,w2][hi,lo]
__device__ __align__(16) unsigned char g_wt[16 * WTILE_BYTES];

__device__ __forceinline__ void red_add_v4(float* addr, float a, float b, float c, float d) {
    asm volatile("red.global.add.v4.f32 [%0], {%1,%2,%3,%4};"
                 :: "l"(addr), "f"(a), "f"(b), "f"(c), "f"(d) : "memory");
}
__device__ __forceinline__ void red_add_v2(float* addr, float a, float b) {
    asm volatile("red.global.add.v2.f32 [%0], {%1,%2};"
                 :: "l"(addr), "f"(a), "f"(b) : "memory");
}

__device__ __forceinline__ uint32_t smem_u32(const void* p) {
    uint32_t a;
    asm("{ .reg .u64 t; cvta.to.shared.u64 t, %1; cvt.u32.u64 %0, t; }" : "=r"(a) : "l"(p));
    return a;
}

__device__ __forceinline__ void ldsm4(uint32_t addr, uint32_t r[4]) {
    asm volatile("ldmatrix.sync.aligned.m8n8.x4.shared.b16 {%0,%1,%2,%3}, [%4];"
                 : "=r"(r[0]), "=r"(r[1]), "=r"(r[2]), "=r"(r[3]) : "r"(addr));
}

__device__ __forceinline__ void mma16816(float d[4], const uint32_t a[4],
                                         uint32_t b0, uint32_t b1) {
    asm volatile(
        "mma.sync.aligned.m16n8k16.row.col.f32.bf16.bf16.f32 "
        "{%0,%1,%2,%3}, {%4,%5,%6,%7}, {%8,%9}, {%0,%1,%2,%3};"
        : "+f"(d[0]), "+f"(d[1]), "+f"(d[2]), "+f"(d[3])
        : "r"(a[0]), "r"(a[1]), "r"(a[2]), "r"(a[3]), "r"(b0), "r"(b1));
}

__device__ __forceinline__ uint32_t pack_bf16_hi(float f0, float f1) {
    return ((uint32_t)__bfloat16_as_ushort(__float2bfloat16_rn(f1)) << 16)
         |  (uint32_t)__bfloat16_as_ushort(__float2bfloat16_rn(f0));
}

// ===========================================================================
// One-time kernels
// ===========================================================================
__global__ void count_edges_kernel(const int* __restrict__ ei, float* __restrict__ cnt) {
    int e = blockIdx.x * 256 + threadIdx.x;
    if (e < N_EDGES) atomicAdd(&cnt[ei[N_EDGES + e]], 1.0f);
}
__global__ void count_batch_kernel(const int* __restrict__ batch, float* __restrict__ bcnt) {
    int n = blockIdx.x * 256 + threadIdx.x;
    if (n < N_NODES) atomicAdd(&bcnt[batch[n]], 1.0f);
}

// Transpose+split W (row-major [K=128, N=128]) into bf16 hi/lo tiles [n][k], LDA pad.
__global__ void prep_weights_kernel(const float* __restrict__ n1w1,
                                    const float* __restrict__ n1w2) {
    int b = blockIdx.x;                 // 0..7: (layer, w1/w2)
    int l = b >> 1, which = b & 1;
    const float* w = (which ? n1w2 : n1w1) + (size_t)l * D * D;
    unsigned char* thi = g_wt + ((size_t)b * 2 + 0) * WTILE_BYTES;
    unsigned char* tlo = g_wt + ((size_t)b * 2 + 1) * WTILE_BYTES;
    for (int idx = threadIdx.x; idx < 128 * 32; idx += 256) {
        int n = idx >> 5, kq = (idx & 31) << 2;
        unsigned short hh[4], ll[4];
#pragma unroll
        for (int q = 0; q < 4; ++q) {
            float f = w[(kq + q) * D + n];
            __nv_bfloat16 h = __float2bfloat16_rn(f);
            float r = f - __bfloat162float(h);
            hh[q] = __bfloat16_as_ushort(h);
            ll[q] = __bfloat16_as_ushort(__float2bfloat16_rn(r));
        }
        uint32_t o = (uint32_t)(n * LDA + kq) * 2;
        *(uint2*)(thi + o) = make_uint2(((uint32_t)hh[1] << 16) | hh[0],
                                        ((uint32_t)hh[3] << 16) | hh[2]);
        *(uint2*)(tlo + o) = make_uint2(((uint32_t)ll[1] << 16) | ll[0],
                                        ((uint32_t)ll[3] << 16) | ll[2]);
    }
}

// ===========================================================================
// Edge MLP via mma.sync (split-bf16, 3-term)
// smem layout (bytes)
// ===========================================================================
#define SM_COLS  0                                // int[128]
#define SM_B1    512                              // float[128]
#define SM_B2    1024                             // float[128]
#define A_HI_OFF 2048
#define A_LO_OFF (A_HI_OFF + WTILE_BYTES)
#define W_HI_OFF (A_LO_OFF + WTILE_BYTES)
#define W_LO_OFF (W_HI_OFF + WTILE_BYTES)
static const int EDGE_SMEM = W_LO_OFF + WTILE_BYTES;   // 141312

// One split GEMM pass: D += Ahi@Whi + Ahi@Wlo + Alo@Whi over K=128.
__device__ __forceinline__ void gemm_split(uint32_t aHi, uint32_t aLo,
                                           uint32_t wHi, uint32_t wLo,
                                           int mrow, int ncol, int lane,
                                           float d[2][8][4]) {
    const int a_row  = lane & 15;
    const int a_koff = (lane >> 4) << 3;
    const int b_nrow = ((lane >> 4) << 3) + (lane & 7);
    const int b_koff = ((lane >> 3) & 1) << 3;
#pragma unroll
    for (int ks = 0; ks < 8; ++ks) {
        const int kb = ks * 16;
        uint32_t ah[2][4], al[2][4];
#pragma unroll
        for (int mt = 0; mt < 2; ++mt) {
            uint32_t off = (uint32_t)(((mrow + mt * 16 + a_row) * LDA + kb + a_koff) * 2);
            ldsm4(aHi + off, ah[mt]);
            ldsm4(aLo + off, al[mt]);
        }
#pragma unroll
        for (int p = 0; p < 4; ++p) {   // pairs of n8 tiles
            uint32_t off = (uint32_t)(((ncol + p * 16 + b_nrow) * LDA + kb + b_koff) * 2);
            uint32_t bh[4], bl[4];
            ldsm4(wHi + off, bh);
            ldsm4(wLo + off, bl);
#pragma unroll
            for (int h = 0; h < 2; ++h) {
                const int nt = p * 2 + h;
#pragma unroll
                for (int mt = 0; mt < 2; ++mt) {
                    mma16816(d[mt][nt], ah[mt], bh[2 * h], bh[2 * h + 1]);
                    mma16816(d[mt][nt], ah[mt], bl[2 * h], bl[2 * h + 1]);
                    mma16816(d[mt][nt], al[mt], bh[2 * h], bh[2 * h + 1]);
                }
            }
        }
    }
}

__global__ __launch_bounds__(256, 1)
void edge_mlp_mma_kernel(const float* __restrict__ x, const int* __restrict__ ei,
                         const unsigned char* __restrict__ w1hi, const unsigned char* __restrict__ w1lo,
                         const unsigned char* __restrict__ w2hi, const unsigned char* __restrict__ w2lo,
                         const float* __restrict__ b1, const float* __restrict__ b2,
                         float* __restrict__ agg)
{
    extern __shared__ char smc[];
    int*   colS = (int*)(smc + SM_COLS);
    float* b1s  = (float*)(smc + SM_B1);
    float* b2s  = (float*)(smc + SM_B2);

    const int tid  = threadIdx.x;
    const int warp = tid >> 5;
    const int lane = tid & 31;
    const int e0   = blockIdx.x * 128;

    const uint32_t sbase = smem_u32(smc);
    const uint32_t aHi = sbase + A_HI_OFF, aLo = sbase + A_LO_OFF;
    const uint32_t wHi = sbase + W_HI_OFF, wLo = sbase + W_LO_OFF;

    // ---- gather 128 edge-source rows, split to bf16 hi/lo ----
    for (int r = warp; r < 128; r += 8) {
        int e = e0 + r;
        float4 v = make_float4(0.f, 0.f, 0.f, 0.f);
        if (e < N_EDGES) {
            if (lane == 0) colS[r] = ei[N_EDGES + e];
            v = *((const float4*)(x + (size_t)ei[e] * D) + lane);
        } else if (lane == 0) colS[r] = -1;
        float vv[4] = {v.x, v.y, v.z, v.w};
        unsigned short h[4], lo[4];
#pragma unroll
        for (int q = 0; q < 4; ++q) {
            __nv_bfloat16 hh = __float2bfloat16_rn(vv[q]);
            float rr = vv[q] - __bfloat162float(hh);
            h[q]  = __bfloat16_as_ushort(hh);
            lo[q] = __bfloat16_as_ushort(__float2bfloat16_rn(rr));
        }
        uint32_t o = (uint32_t)(r * LDA + lane * 4) * 2;
        *(uint2*)(smc + A_HI_OFF + o) = make_uint2(((uint32_t)h[1] << 16) | h[0],
                                                   ((uint32_t)h[3] << 16) | h[2]);
        *(uint2*)(smc + A_LO_OFF + o) = make_uint2(((uint32_t)lo[1] << 16) | lo[0],
                                                   ((uint32_t)lo[3] << 16) | lo[2]);
    }

    // ---- W1 tiles + biases into smem ----
    {
        uint4* dh = (uint4*)(smc + W_HI_OFF);
        uint4* dl = (uint4*)(smc + W_LO_OFF);
        const uint4* sh = (const uint4*)w1hi;
        const uint4* sl = (const uint4*)w1lo;
        for (int i = tid; i < WTILE_BYTES / 16; i += 256) { dh[i] = sh[i]; dl[i] = sl[i]; }
        if (tid < 128) { b1s[tid] = b1[tid]; b2s[tid] = b2[tid]; }
    }
    __syncthreads();

    const int mrow = (warp >> 1) * 32;   // 4 warps down M
    const int ncol = (warp & 1) * 64;    // 2 warps across N

    float d[2][8][4];
#pragma unroll
    for (int mt = 0; mt < 2; ++mt)
#pragma unroll
        for (int nt = 0; nt < 8; ++nt)
#pragma unroll
            for (int q = 0; q < 4; ++q) d[mt][nt][q] = 0.f;

    // ---- GEMM1: D1 = A @ W1 (3-term split) ----
    gemm_split(aHi, aLo, wHi, wLo, mrow, ncol, lane, d);

    __syncthreads();   // everyone done reading A smem before T overwrites it

    // ---- Epilogue 1: bias+relu, re-split, T -> A smem buffers ----
    {
        const int crow = lane >> 2;
        const int ccol = (lane & 3) * 2;
#pragma unroll
        for (int mt = 0; mt < 2; ++mt) {
#pragma unroll
            for (int nt = 0; nt < 8; ++nt) {
                const int row = mrow + mt * 16 + crow;
                const int col = ncol + nt * 8 + ccol;
                float f0 = fmaxf(d[mt][nt][0] + b1s[col],     0.f);
                float f1 = fmaxf(d[mt][nt][1] + b1s[col + 1], 0.f);
                float f2 = fmaxf(d[mt][nt][2] + b1s[col],     0.f);
                float f3 = fmaxf(d[mt][nt][3] + b1s[col + 1], 0.f);
                uint32_t o0 = (uint32_t)(row * LDA + col) * 2;
                uint32_t o1 = (uint32_t)((row + 8) * LDA + col) * 2;
                *(uint32_t*)(smc + A_HI_OFF + o0) = pack_bf16_hi(f0, f1);
                *(uint32_t*)(smc + A_HI_OFF + o1) = pack_bf16_hi(f2, f3);
                float r0 = f0 - __bfloat162float(__float2bfloat16_rn(f0));
                float r1 = f1 - __bfloat162float(__float2bfloat16_rn(f1));
                float r2 = f2 - __bfloat162float(__float2bfloat16_rn(f2));
                float r3 = f3 - __bfloat162float(__float2bfloat16_rn(f3));
                *(uint32_t*)(smc + A_LO_OFF + o0) = pack_bf16_hi(r0, r1);
                *(uint32_t*)(smc + A_LO_OFF + o1) = pack_bf16_hi(r2, r3);
            }
        }
    }

    // ---- swap in W2 tiles ----
    {
        uint4* dh = (uint4*)(smc + W_HI_OFF);
        uint4* dl = (uint4*)(smc + W_LO_OFF);
        const uint4* sh = (const uint4*)w2hi;
        const uint4* sl = (const uint4*)w2lo;
        for (int i = tid; i < WTILE_BYTES / 16; i += 256) { dh[i] = sh[i]; dl[i] = sl[i]; }
    }
    __syncthreads();

#pragma unroll
    for (int mt = 0; mt < 2; ++mt)
#pragma unroll
        for (int nt = 0; nt < 8; ++nt)
#pragma unroll
            for (int q = 0; q < 4; ++q) d[mt][nt][q] = 0.f;

    // ---- GEMM2: D2 = T @ W2 ----
    gemm_split(aHi, aLo, wHi, wLo, mrow, ncol, lane, d);

    // ---- Epilogue 2: bias + red.v2 scatter into agg[col] ----
    {
        const int crow = lane >> 2;
        const int ccol = (lane & 3) * 2;
#pragma unroll
        for (int mt = 0; mt < 2; ++mt) {
            const int row0 = mrow + mt * 16 + crow;
            const int c0 = colS[row0];
            const int c1 = colS[row0 + 8];
#pragma unroll
            for (int nt = 0; nt < 8; ++nt) {
                const int col = ncol + nt * 8 + ccol;
                if (c0 >= 0)
                    red_add_v2(agg + (size_t)c0 * D + col,
                               d[mt][nt][0] + b2s[col], d[mt][nt][1] + b2s[col + 1]);
                if (c1 >= 0)
                    red_add_v2(agg + (size_t)c1 * D + col,
                               d[mt][nt][2] + b2s[col], d[mt][nt][3] + b2s[col + 1]);
            }
        }
    }
}

// ===========================================================================
// Node MLP (FFMA; occupancy 2)
// ===========================================================================
__global__ __launch_bounds__(256, 2)
void node_mlp_kernel(const float* __restrict__ x,
                     const float* __restrict__ agg,
                     const float* __restrict__ cnt,
                     const float* __restrict__ u,
                     const int* __restrict__ batch,
                     const float* __restrict__ w1, const float* __restrict__ b1,
                     const float* __restrict__ w2, const float* __restrict__ b2,
                     float* __restrict__ xout,
                     float* __restrict__ xsum)
{
    extern __shared__ float sm[];
    float* Hc  = sm;                       // [128][HPAD]
    float* Ws  = Hc + 128 * HPAD;          // [32][128]
    float* Ts  = Ws + 32 * 128;            // [128][EPAD]
    float* rcp = Ts + 128 * EPAD;          // [128]
    int*   bat = (int*)(rcp + 128);        // [128]

    const int tid = threadIdx.x;
    const int tx  = tid & 15;
    const int ty  = tid >> 4;
    const int n0  = blockIdx.x * 128;

    if (tid < 128) {
        int n = n0 + tid;
        if (n < N_NODES) {
            rcp[tid] = 1.0f / fmaxf(cnt[n], 1.0f);
            bat[tid] = batch[n];
        } else {
            rcp[tid] = 0.f;
            bat[tid] = 0;
        }
    }
    __syncthreads();

    float acc[8][8];
#pragma unroll
    for (int i = 0; i < 8; ++i)
#pragma unroll
        for (int j = 0; j < 8; ++j) acc[i][j] = 0.f;

    for (int kk = 0; kk < 384; kk += 32) {
        if (kk < 128) {
            for (int idx = tid; idx < 128 * 32; idx += 256) {
                int r = idx >> 5, k = idx & 31, n = n0 + r;
                Hc[r * HPAD + k] = (n < N_NODES) ? x[(size_t)n * D + kk + k] : 0.f;
            }
        } else if (kk < 256) {
            for (int idx = tid; idx < 128 * 32; idx += 256) {
                int r = idx >> 5, k = idx & 31, n = n0 + r;
                Hc[r * HPAD + k] = (n < N_NODES) ? agg[(size_t)n * D + (kk - 128) + k] * rcp[r] : 0.f;
            }
        } else {
            for (int idx = tid; idx < 128 * 32; idx += 256) {
                int r = idx >> 5, k = idx & 31, n = n0 + r;
                Hc[r * HPAD + k] = (n < N_NODES) ? u[bat[r] * D + (kk - 256) + k] : 0.f;
            }
        }
#pragma unroll 4
        for (int idx = tid; idx < 32 * 128; idx += 256) Ws[idx] = w1[kk * 128 + idx];
        __syncthreads();
#pragma unroll 4
        for (int k = 0; k < 32; ++k) {
            float ra[8];
#pragma unroll
            for (int i = 0; i < 8; ++i) ra[i] = Hc[(ty * 8 + i) * HPAD + k];
            float4 rb0 = *(const float4*)&Ws[k * 128 + tx * 8];
            float4 rb1 = *(const float4*)&Ws[k * 128 + tx * 8 + 4];
            float rb[8] = {rb0.x, rb0.y, rb0.z, rb0.w, rb1.x, rb1.y, rb1.z, rb1.w};
#pragma unroll
            for (int i = 0; i < 8; ++i)
#pragma unroll
                for (int j = 0; j < 8; ++j) acc[i][j] = fmaf(ra[i], rb[j], acc[i][j]);
        }
        __syncthreads();
    }

    {
        float bv[8];
#pragma unroll
        for (int j = 0; j < 8; ++j) bv[j] = b1[tx * 8 + j];
#pragma unroll
        for (int i = 0; i < 8; ++i) {
#pragma unroll
            for (int j = 0; j < 8; ++j) acc[i][j] = fmaxf(acc[i][j] + bv[j], 0.f);
            *(float4*)&Ts[(ty * 8 + i) * EPAD + tx * 8]     = make_float4(acc[i][0], acc[i][1], acc[i][2], acc[i][3]);
            *(float4*)&Ts[(ty * 8 + i) * EPAD + tx * 8 + 4] = make_float4(acc[i][4], acc[i][5], acc[i][6], acc[i][7]);
        }
    }

#pragma unroll
    for (int i = 0; i < 8; ++i)
#pragma unroll
        for (int j = 0; j < 8; ++j) acc[i][j] = 0.f;

    for (int kk = 0; kk < D; kk += 32) {
#pragma unroll 4
        for (int idx = tid; idx < 32 * 128; idx += 256) Ws[idx] = w2[kk * 128 + idx];
        __syncthreads();
#pragma unroll 4
        for (int k = 0; k < 32; ++k) {
            float ra[8];
#pragma unroll
            for (int i = 0; i < 8; ++i) ra[i] = Ts[(ty * 8 + i) * EPAD + kk + k];
            float4 rb0 = *(const float4*)&Ws[k * 128 + tx * 8];
            float4 rb1 = *(const float4*)&Ws[k * 128 + tx * 8 + 4];
            float rb[8] = {rb0.x, rb0.y, rb0.z, rb0.w, rb1.x, rb1.y, rb1.z, rb1.w};
#pragma unroll
            for (int i = 0; i < 8; ++i)
#pragma unroll
                for (int j = 0; j < 8; ++j) acc[i][j] = fmaf(ra[i], rb[j], acc[i][j]);
        }
        __syncthreads();
    }

    {
        float bv[8];
#pragma unroll
        for (int j = 0; j < 8; ++j) bv[j] = b2[tx * 8 + j];
#pragma unroll
        for (int i = 0; i < 8; ++i) {
            int r = ty * 8 + i;
            int n = n0 + r;
            if (n < N_NODES) {
                float o[8];
#pragma unroll
                for (int j = 0; j < 8; ++j) o[j] = acc[i][j] + bv[j];
                *(float4*)&xout[(size_t)n * D + tx * 8]     = make_float4(o[0], o[1], o[2], o[3]);
                *(float4*)&xout[(size_t)n * D + tx * 8 + 4] = make_float4(o[4], o[5], o[6], o[7]);
                float* sbase = xsum + (size_t)bat[r] * D + tx * 8;
                red_add_v4(sbase,     o[0], o[1], o[2], o[3]);
                red_add_v4(sbase + 4, o[4], o[5], o[6], o[7]);
            }
        }
    }
}

// ===========================================================================
// Global MLP (unchanged)
// ===========================================================================
__global__ __launch_bounds__(256, 1)
void global_mlp_kernel(const float* __restrict__ u,
                       const float* __restrict__ xsum,
                       const float* __restrict__ bcnt,
                       const float* __restrict__ w1, const float* __restrict__ b1,
                       const float* __restrict__ w2, const float* __restrict__ b2,
                       float* __restrict__ uout)
{
    extern __shared__ float sm[];
    float* G  = sm;              // [64][256]
    float* Hh = G + 64 * 256;    // [64][EPAD]

    const int tid = threadIdx.x;
    const int tx  = tid & 15;
    const int ty  = tid >> 4;

    for (int idx = tid; idx < 64 * 128; idx += 256) {
        int b = idx >> 7, c = idx & 127;
        G[b * 256 + c]       = u[idx];
        G[b * 256 + 128 + c] = xsum[idx] / fmaxf(bcnt[b], 1.0f);
    }
    __syncthreads();

    float acc[4][8];
#pragma unroll
    for (int i = 0; i < 4; ++i)
#pragma unroll
        for (int j = 0; j < 8; ++j) acc[i][j] = 0.f;

#pragma unroll 4
    for (int k = 0; k < 256; ++k) {
        float ra[4];
#pragma unroll
        for (int i = 0; i < 4; ++i) ra[i] = G[(ty * 4 + i) * 256 + k];
        float4 rb0 = __ldg((const float4*)&w1[k * 128 + tx * 8]);
        float4 rb1 = __ldg((const float4*)&w1[k * 128 + tx * 8 + 4]);
        float rb[8] = {rb0.x, rb0.y, rb0.z, rb0.w, rb1.x, rb1.y, rb1.z, rb1.w};
#pragma unroll
        for (int i = 0; i < 4; ++i)
#pragma unroll
            for (int j = 0; j < 8; ++j) acc[i][j] = fmaf(ra[i], rb[j], acc[i][j]);
    }

    {
        float bv[8];
#pragma unroll
        for (int j = 0; j < 8; ++j) bv[j] = b1[tx * 8 + j];
#pragma unroll
        for (int i = 0; i < 4; ++i) {
#pragma unroll
            for (int j = 0; j < 8; ++j) acc[i][j] = fmaxf(acc[i][j] + bv[j], 0.f);
            *(float4*)&Hh[(ty * 4 + i) * EPAD + tx * 8]     = make_float4(acc[i][0], acc[i][1], acc[i][2], acc[i][3]);
            *(float4*)&Hh[(ty * 4 + i) * EPAD + tx * 8 + 4] = make_float4(acc[i][4], acc[i][5], acc[i][6], acc[i][7]);
        }
    }
    __syncthreads();

#pragma unroll
    for (int i = 0; i < 4; ++i)
#pragma unroll
        for (int j = 0; j < 8; ++j) acc[i][j] = 0.f;

#pragma unroll 4
    for (int k = 0; k < 128; ++k) {
        float ra[4];
#pragma unroll
        for (int i = 0; i < 4; ++i) ra[i] = Hh[(ty * 4 + i) * EPAD + k];
        float4 rb0 = __ldg((const float4*)&w2[k * 128 + tx * 8]);
        float4 rb1 = __ldg((const float4*)&w2[k * 128 + tx * 8 + 4]);
        float rb[8] = {rb0.x, rb0.y, rb0.z, rb0.w, rb1.x, rb1.y, rb1.z, rb1.w};
#pragma unroll
        for (int i = 0; i < 4; ++i)
#pragma unroll
            for (int j = 0; j < 8; ++j) acc[i][j] = fmaf(ra[i], rb[j], acc[i][j]);
    }

    {
        float bv[8];
#pragma unroll
        for (int j = 0; j < 8; ++j) bv[j] = b2[tx * 8 + j];
#pragma unroll
        for (int i = 0; i < 4; ++i) {
            int b = ty * 4 + i;
            *(float4*)&uout[b * D + tx * 8]     = make_float4(acc[i][0] + bv[0], acc[i][1] + bv[1],
                                                              acc[i][2] + bv[2], acc[i][3] + bv[3]);
            *(float4*)&uout[b * D + tx * 8 + 4] = make_float4(acc[i][4] + bv[4], acc[i][5] + bv[5],
                                                              acc[i][6] + bv[6], acc[i][7] + bv[7]);
        }
    }
}

// ===========================================================================
// Host side
// ===========================================================================
static const int NODE_SMEM = (128 * HPAD + 32 * 128 + 128 * EPAD + 128) * 4 + 128 * 4;
static const int GLOB_SMEM = (64 * 256 + 64 * EPAD) * 4;

extern "C" void kernel_launch(void* const* d_in, const int* in_sizes, int n_in,
                              void* d_out, int out_size) {
    const float* x0    = (const float*)d_in[0];
    const int*   ei    = (const int*)d_in[1];      // int32 (JAX x64 disabled)
    const float* u0    = (const float*)d_in[2];
    const int*   batch = (const int*)d_in[3];      // int32
    const float* n1w1 = (const float*)d_in[4];
    const float* n1b1 = (const float*)d_in[5];
    const float* n1w2 = (const float*)d_in[6];
    const float* n1b2 = (const float*)d_in[7];
    const float* n2w1 = (const float*)d_in[8];
    const float* n2b1 = (const float*)d_in[9];
    const float* n2w2 = (const float*)d_in[10];
    const float* n2b2 = (const float*)d_in[11];
    const float* gw1  = (const float*)d_in[12];
    const float* gb1  = (const float*)d_in[13];
    const float* gw2  = (const float*)d_in[14];
    const float* gb2  = (const float*)d_in[15];
    float* out = (float*)d_out;

    float *px, *pu, *pagg, *pcnt, *pxsum, *pbcnt;
    unsigned char* pwt;
    cudaGetSymbolAddress((void**)&px,    g_x);
    cudaGetSymbolAddress((void**)&pu,    g_u);
    cudaGetSymbolAddress((void**)&pagg,  g_agg);
    cudaGetSymbolAddress((void**)&pcnt,  g_cnt);
    cudaGetSymbolAddress((void**)&pxsum, g_xsum);
    cudaGetSymbolAddress((void**)&pbcnt, g_bcnt);
    cudaGetSymbolAddress((void**)&pwt,   g_wt);
    float* xbuf[2] = {px, px + (size_t)N_NODES * D};
    float* ubuf[2] = {pu, pu + (size_t)NB * D};

    cudaFuncSetAttribute(edge_mlp_mma_kernel, cudaFuncAttributeMaxDynamicSharedMemorySize, EDGE_SMEM);
    cudaFuncSetAttribute(node_mlp_kernel,     cudaFuncAttributeMaxDynamicSharedMemorySize, NODE_SMEM);
    cudaFuncSetAttribute(global_mlp_kernel,   cudaFuncAttributeMaxDynamicSharedMemorySize, GLOB_SMEM);

    // one-time per launch: counts + weight tiles
    cudaMemsetAsync(pcnt,  0, N_NODES * sizeof(float));
    cudaMemsetAsync(pbcnt, 0, NB * sizeof(float));
    count_edges_kernel<<<(N_EDGES + 255) / 256, 256>>>(ei, pcnt);
    count_batch_kernel<<<(N_NODES + 255) / 256, 256>>>(batch, pbcnt);
    prep_weights_kernel<<<2 * NLAYERS, 256>>>(n1w1, n1w2);

    const float* xc = x0;
    const float* uc = u0;
    for (int l = 0; l < NLAYERS; ++l) {
        cudaMemsetAsync(pagg,  0, (size_t)N_NODES * D * sizeof(float));
        cudaMemsetAsync(pxsum, 0, (size_t)NB * D * sizeof(float));

        const unsigned char* w1hi = pwt + (size_t)(l * 4 + 0) * WTILE_BYTES;
        const unsigned char* w1lo = pwt + (size_t)(l * 4 + 1) * WTILE_BYTES;
        const unsigned char* w2hi = pwt + (size_t)(l * 4 + 2) * WTILE_BYTES;
        const unsigned char* w2lo = pwt + (size_t)(l * 4 + 3) * WTILE_BYTES;

        edge_mlp_mma_kernel<<<(N_EDGES + 127) / 128, 256, EDGE_SMEM>>>(
            xc, ei, w1hi, w1lo, w2hi, w2lo,
            n1b1 + (size_t)l * D, n1b2 + (size_t)l * D, pagg);

        float* xn = (l == NLAYERS - 1) ? out : xbuf[l & 1];
        node_mlp_kernel<<<(N_NODES + 127) / 128, 256, NODE_SMEM>>>(
            xc, pagg, pcnt, uc, batch,
            n2w1 + (size_t)l * 384 * D, n2b1 + (size_t)l * D,
            n2w2 + (size_t)l * D * D,   n2b2 + (size_t)l * D,
            xn, pxsum);

        float* un = (l == NLAYERS - 1) ? out + (size_t)N_NODES * D : ubuf[l & 1];
        global_mlp_kernel<<<1, 256, GLOB_SMEM>>>(
            uc, pxsum, pbcnt,
            gw1 + (size_t)l * 256 * D, gb1 + (size_t)l * D,
            gw2 + (size_t)l * D * D,   gb2 + (size_t)l * D,
            un);

        xc = xn;
        uc = un;
    }
}

// round 10
// speedup vs baseline: 1.1565x; 1.1565x over previous
#include <cuda_runtime.h>
#include <cuda_bf16.h>
#include <cstdint>

#define N_NODES 50000
#define N_EDGES 600000
#define NB      64
#define D       128      // F == H == U
#define NLAYERS 4

#define EPAD 132   // padded row stride for 128-wide smem tiles (node/global)
#define HPAD 36    // padded row stride for 32-wide K chunks (node)

#define LDA 136                      // bf16 row stride for mma tiles (272B, 16B-aligned)
#define WTILE_BYTES (128 * LDA * 2)  // 34816 bytes per 128x128 bf16 tile

// ===========================================================================
// Scratch (no allocations allowed -> __device__ globals)
// ===========================================================================
__device__ float g_x[2][N_NODES * D];
__device__ float g_u[2][NB * D];
__device__ float g_agg[N_NODES * D];
__device__ float g_cnt[N_NODES];
__device__ float g_xsum[NB * D];
__device__ float g_bcnt[NB];
// transposed/split bf16 weight tiles [n][k], padded LDA: [layer][w1,w2][hi,lo]
__device__ __align__(16) unsigned char g_wt[16 * WTILE_BYTES];

__device__ __forceinline__ void red_add_v4(float* addr, float a, float b, float c, float d) {
    asm volatile("red.global.add.v4.f32 [%0], {%1,%2,%3,%4};"
                 :: "l"(addr), "f"(a), "f"(b), "f"(c), "f"(d) : "memory");
}
__device__ __forceinline__ void red_add_v2(float* addr, float a, float b) {
    asm volatile("red.global.add.v2.f32 [%0], {%1,%2};"
                 :: "l"(addr), "f"(a), "f"(b) : "memory");
}

__device__ __forceinline__ uint32_t smem_u32(const void* p) {
    uint32_t a;
    asm("{ .reg .u64 t; cvta.to.shared.u64 t, %1; cvt.u32.u64 %0, t; }" : "=r"(a) : "l"(p));
    return a;
}

__device__ __forceinline__ void ldsm4(uint32_t addr, uint32_t r[4]) {
    asm volatile("ldmatrix.sync.aligned.m8n8.x4.shared.b16 {%0,%1,%2,%3}, [%4];"
                 : "=r"(r[0]), "=r"(r[1]), "=r"(r[2]), "=r"(r[3]) : "r"(addr));
}

__device__ __forceinline__ void mma16816(float d[4], const uint32_t a[4],
                                         uint32_t b0, uint32_t b1) {
    asm volatile(
        "mma.sync.aligned.m16n8k16.row.col.f32.bf16.bf16.f32 "
        "{%0,%1,%2,%3}, {%4,%5,%6,%7}, {%8,%9}, {%0,%1,%2,%3};"
        : "+f"(d[0]), "+f"(d[1]), "+f"(d[2]), "+f"(d[3])
        : "r"(a[0]), "r"(a[1]), "r"(a[2]), "r"(a[3]), "r"(b0), "r"(b1));
}

__device__ __forceinline__ uint32_t pack_bf16_hi(float f0, float f1) {
    return ((uint32_t)__bfloat16_as_ushort(__float2bfloat16_rn(f1)) << 16)
         |  (uint32_t)__bfloat16_as_ushort(__float2bfloat16_rn(f0));
}

// ===========================================================================
// One-time kernels
// ===========================================================================
__global__ void count_edges_kernel(const int* __restrict__ ei, float* __restrict__ cnt) {
    int e = blockIdx.x * 256 + threadIdx.x;
    if (e < N_EDGES) atomicAdd(&cnt[ei[N_EDGES + e]], 1.0f);
}
__global__ void count_batch_kernel(const int* __restrict__ batch, float* __restrict__ bcnt) {
    int n = blockIdx.x * 256 + threadIdx.x;
    if (n < N_NODES) atomicAdd(&bcnt[batch[n]], 1.0f);
}

// Transpose+split W (row-major [K=128, N=128]) into bf16 hi/lo tiles [n][k], LDA pad.
__global__ void prep_weights_kernel(const float* __restrict__ n1w1,
                                    const float* __restrict__ n1w2) {
    int b = blockIdx.x;                 // 0..7: (layer, w1/w2)
    int l = b >> 1, which = b & 1;
    const float* w = (which ? n1w2 : n1w1) + (size_t)l * D * D;
    unsigned char* thi = g_wt + ((size_t)b * 2 + 0) * WTILE_BYTES;
    unsigned char* tlo = g_wt + ((size_t)b * 2 + 1) * WTILE_BYTES;
    for (int idx = threadIdx.x; idx < 128 * 32; idx += 256) {
        int n = idx >> 5, kq = (idx & 31) << 2;
        unsigned short hh[4], ll[4];
#pragma unroll
        for (int q = 0; q < 4; ++q) {
            float f = w[(kq + q) * D + n];
            __nv_bfloat16 h = __float2bfloat16_rn(f);
            float r = f - __bfloat162float(h);
            hh[q] = __bfloat16_as_ushort(h);
            ll[q] = __bfloat16_as_ushort(__float2bfloat16_rn(r));
        }
        uint32_t o = (uint32_t)(n * LDA + kq) * 2;
        *(uint2*)(thi + o) = make_uint2(((uint32_t)hh[1] << 16) | hh[0],
                                        ((uint32_t)hh[3] << 16) | hh[2]);
        *(uint2*)(tlo + o) = make_uint2(((uint32_t)ll[1] << 16) | ll[0],
                                        ((uint32_t)ll[3] << 16) | ll[2]);
    }
}

// ===========================================================================
// Edge MLP via mma.sync (split-bf16, 3-term), 512 threads, 4x4 warp grid
// ===========================================================================
#define SM_COLS  0                                // int[128]
#define SM_B1    512                              // float[128]
#define SM_B2    1024                             // float[128]
#define A_HI_OFF 2048
#define A_LO_OFF (A_HI_OFF + WTILE_BYTES)
#define W_HI_OFF (A_LO_OFF + WTILE_BYTES)
#define W_LO_OFF (W_HI_OFF + WTILE_BYTES)
static const int EDGE_SMEM = W_LO_OFF + WTILE_BYTES;   // 141312
#define ETHREADS 512

// One split GEMM pass over K=128: D += Ahi@Whi + Ahi@Wlo + Alo@Whi.
// Warp tile 32x32: d[2 m16][4 n8][4].
__device__ __forceinline__ void gemm_split32(uint32_t aHi, uint32_t aLo,
                                             uint32_t wHi, uint32_t wLo,
                                             int mrow, int ncol, int lane,
                                             float d[2][4][4]) {
    const int a_row  = lane & 15;
    const int a_koff = (lane >> 4) << 3;
    const int b_nrow = ((lane >> 4) << 3) + (lane & 7);
    const int b_koff = ((lane >> 3) & 1) << 3;
#pragma unroll
    for (int ks = 0; ks < 8; ++ks) {
        const int kb = ks * 16;
        uint32_t ah[2][4], al[2][4];
#pragma unroll
        for (int mt = 0; mt < 2; ++mt) {
            uint32_t off = (uint32_t)(((mrow + mt * 16 + a_row) * LDA + kb + a_koff) * 2);
            ldsm4(aHi + off, ah[mt]);
            ldsm4(aLo + off, al[mt]);
        }
#pragma unroll
        for (int p = 0; p < 2; ++p) {   // pairs of n8 tiles
            uint32_t off = (uint32_t)(((ncol + p * 16 + b_nrow) * LDA + kb + b_koff) * 2);
            uint32_t bh[4], bl[4];
            ldsm4(wHi + off, bh);
            ldsm4(wLo + off, bl);
#pragma unroll
            for (int h = 0; h < 2; ++h) {
                const int nt = p * 2 + h;
#pragma unroll
                for (int mt = 0; mt < 2; ++mt) {
                    mma16816(d[mt][nt], ah[mt], bh[2 * h], bh[2 * h + 1]);
                    mma16816(d[mt][nt], ah[mt], bl[2 * h], bl[2 * h + 1]);
                    mma16816(d[mt][nt], al[mt], bh[2 * h], bh[2 * h + 1]);
                }
            }
        }
    }
}

__global__ __launch_bounds__(ETHREADS, 1)
void edge_mlp_mma_kernel(const float* __restrict__ x, const int* __restrict__ ei,
                         const unsigned char* __restrict__ w1hi, const unsigned char* __restrict__ w1lo,
                         const unsigned char* __restrict__ w2hi, const unsigned char* __restrict__ w2lo,
                         const float* __restrict__ b1, const float* __restrict__ b2,
                         float* __restrict__ agg)
{
    extern __shared__ char smc[];
    int*   colS = (int*)(smc + SM_COLS);
    float* b1s  = (float*)(smc + SM_B1);
    float* b2s  = (float*)(smc + SM_B2);

    const int tid  = threadIdx.x;
    const int warp = tid >> 5;
    const int lane = tid & 31;
    const int e0   = blockIdx.x * 128;

    const uint32_t sbase = smem_u32(smc);
    const uint32_t aHi = sbase + A_HI_OFF, aLo = sbase + A_LO_OFF;
    const uint32_t wHi = sbase + W_HI_OFF, wLo = sbase + W_LO_OFF;

    // ---- gather 128 edge-source rows, split to bf16 hi/lo ----
    for (int r = warp; r < 128; r += 16) {
        int e = e0 + r;
        float4 v = make_float4(0.f, 0.f, 0.f, 0.f);
        if (e < N_EDGES) {
            if (lane == 0) colS[r] = ei[N_EDGES + e];
            v = *((const float4*)(x + (size_t)ei[e] * D) + lane);
        } else if (lane == 0) colS[r] = -1;
        float vv[4] = {v.x, v.y, v.z, v.w};
        unsigned short h[4], lo[4];
#pragma unroll
        for (int q = 0; q < 4; ++q) {
            __nv_bfloat16 hh = __float2bfloat16_rn(vv[q]);
            float rr = vv[q] - __bfloat162float(hh);
            h[q]  = __bfloat16_as_ushort(hh);
            lo[q] = __bfloat16_as_ushort(__float2bfloat16_rn(rr));
        }
        uint32_t o = (uint32_t)(r * LDA + lane * 4) * 2;
        *(uint2*)(smc + A_HI_OFF + o) = make_uint2(((uint32_t)h[1] << 16) | h[0],
                                                   ((uint32_t)h[3] << 16) | h[2]);
        *(uint2*)(smc + A_LO_OFF + o) = make_uint2(((uint32_t)lo[1] << 16) | lo[0],
                                                   ((uint32_t)lo[3] << 16) | lo[2]);
    }

    // ---- W1 tiles + biases into smem ----
    {
        uint4* dh = (uint4*)(smc + W_HI_OFF);
        uint4* dl = (uint4*)(smc + W_LO_OFF);
        const uint4* sh = (const uint4*)w1hi;
        const uint4* sl = (const uint4*)w1lo;
        for (int i = tid; i < WTILE_BYTES / 16; i += ETHREADS) { dh[i] = sh[i]; dl[i] = sl[i]; }
        if (tid < 128) { b1s[tid] = b1[tid]; b2s[tid] = b2[tid]; }
    }
    __syncthreads();

    const int mrow = (warp >> 2) * 32;   // 4 warps down M
    const int ncol = (warp & 3) * 32;    // 4 warps across N

    float d[2][4][4];
#pragma unroll
    for (int mt = 0; mt < 2; ++mt)
#pragma unroll
        for (int nt = 0; nt < 4; ++nt)
#pragma unroll
            for (int q = 0; q < 4; ++q) d[mt][nt][q] = 0.f;

    // ---- GEMM1: D1 = A @ W1 (3-term split) ----
    gemm_split32(aHi, aLo, wHi, wLo, mrow, ncol, lane, d);

    __syncthreads();   // everyone done reading A smem before T overwrites it

    // ---- Epilogue 1: bias+relu, re-split, T -> A smem buffers ----
    {
        const int crow = lane >> 2;
        const int ccol = (lane & 3) * 2;
#pragma unroll
        for (int mt = 0; mt < 2; ++mt) {
#pragma unroll
            for (int nt = 0; nt < 4; ++nt) {
                const int row = mrow + mt * 16 + crow;
                const int col = ncol + nt * 8 + ccol;
                float f0 = fmaxf(d[mt][nt][0] + b1s[col],     0.f);
                float f1 = fmaxf(d[mt][nt][1] + b1s[col + 1], 0.f);
                float f2 = fmaxf(d[mt][nt][2] + b1s[col],     0.f);
                float f3 = fmaxf(d[mt][nt][3] + b1s[col + 1], 0.f);
                uint32_t o0 = (uint32_t)(row * LDA + col) * 2;
                uint32_t o1 = (uint32_t)((row + 8) * LDA + col) * 2;
                *(uint32_t*)(smc + A_HI_OFF + o0) = pack_bf16_hi(f0, f1);
                *(uint32_t*)(smc + A_HI_OFF + o1) = pack_bf16_hi(f2, f3);
                float r0 = f0 - __bfloat162float(__float2bfloat16_rn(f0));
                float r1 = f1 - __bfloat162float(__float2bfloat16_rn(f1));
                float r2 = f2 - __bfloat162float(__float2bfloat16_rn(f2));
                float r3 = f3 - __bfloat162float(__float2bfloat16_rn(f3));
                *(uint32_t*)(smc + A_LO_OFF + o0) = pack_bf16_hi(r0, r1);
                *(uint32_t*)(smc + A_LO_OFF + o1) = pack_bf16_hi(r2, r3);
            }
        }
    }

    // ---- swap in W2 tiles ----
    {
        uint4* dh = (uint4*)(smc + W_HI_OFF);
        uint4* dl = (uint4*)(smc + W_LO_OFF);
        const uint4* sh = (const uint4*)w2hi;
        const uint4* sl = (const uint4*)w2lo;
        for (int i = tid; i < WTILE_BYTES / 16; i += ETHREADS) { dh[i] = sh[i]; dl[i] = sl[i]; }
    }
    __syncthreads();

#pragma unroll
    for (int mt = 0; mt < 2; ++mt)
#pragma unroll
        for (int nt = 0; nt < 4; ++nt)
#pragma unroll
            for (int q = 0; q < 4; ++q) d[mt][nt][q] = 0.f;

    // ---- GEMM2: D2 = T @ W2 ----
    gemm_split32(aHi, aLo, wHi, wLo, mrow, ncol, lane, d);

    // ---- Epilogue 2: bias + red.v2 scatter into agg[col] ----
    {
        const int crow = lane >> 2;
        const int ccol = (lane & 3) * 2;
#pragma unroll
        for (int mt = 0; mt < 2; ++mt) {
            const int row0 = mrow + mt * 16 + crow;
            const int c0 = colS[row0];
            const int c1 = colS[row0 + 8];
#pragma unroll
            for (int nt = 0; nt < 4; ++nt) {
                const int col = ncol + nt * 8 + ccol;
                if (c0 >= 0)
                    red_add_v2(agg + (size_t)c0 * D + col,
                               d[mt][nt][0] + b2s[col], d[mt][nt][1] + b2s[col + 1]);
                if (c1 >= 0)
                    red_add_v2(agg + (size_t)c1 * D + col,
                               d[mt][nt][2] + b2s[col], d[mt][nt][3] + b2s[col + 1]);
            }
        }
    }
}

// ===========================================================================
// Node MLP (FFMA; occupancy 2)
// ===========================================================================
__global__ __launch_bounds__(256, 2)
void node_mlp_kernel(const float* __restrict__ x,
                     const float* __restrict__ agg,
                     const float* __restrict__ cnt,
                     const float* __restrict__ u,
                     const int* __restrict__ batch,
                     const float* __restrict__ w1, const float* __restrict__ b1,
                     const float* __restrict__ w2, const float* __restrict__ b2,
                     float* __restrict__ xout,
                     float* __restrict__ xsum)
{
    extern __shared__ float sm[];
    float* Hc  = sm;                       // [128][HPAD]
    float* Ws  = Hc + 128 * HPAD;          // [32][128]
    float* Ts  = Ws + 32 * 128;            // [128][EPAD]
    float* rcp = Ts + 128 * EPAD;          // [128]
    int*   bat = (int*)(rcp + 128);        // [128]

    const int tid = threadIdx.x;
    const int tx  = tid & 15;
    const int ty  = tid >> 4;
    const int n0  = blockIdx.x * 128;

    if (tid < 128) {
        int n = n0 + tid;
        if (n < N_NODES) {
            rcp[tid] = 1.0f / fmaxf(cnt[n], 1.0f);
            bat[tid] = batch[n];
        } else {
            rcp[tid] = 0.f;
            bat[tid] = 0;
        }
    }
    __syncthreads();

    float acc[8][8];
#pragma unroll
    for (int i = 0; i < 8; ++i)
#pragma unroll
        for (int j = 0; j < 8; ++j) acc[i][j] = 0.f;

    for (int kk = 0; kk < 384; kk += 32) {
        if (kk < 128) {
            for (int idx = tid; idx < 128 * 32; idx += 256) {
                int r = idx >> 5, k = idx & 31, n = n0 + r;
                Hc[r * HPAD + k] = (n < N_NODES) ? x[(size_t)n * D + kk + k] : 0.f;
            }
        } else if (kk < 256) {
            for (int idx = tid; idx < 128 * 32; idx += 256) {
                int r = idx >> 5, k = idx & 31, n = n0 + r;
                Hc[r * HPAD + k] = (n < N_NODES) ? agg[(size_t)n * D + (kk - 128) + k] * rcp[r] : 0.f;
            }
        } else {
            for (int idx = tid; idx < 128 * 32; idx += 256) {
                int r = idx >> 5, k = idx & 31, n = n0 + r;
                Hc[r * HPAD + k] = (n < N_NODES) ? u[bat[r] * D + (kk - 256) + k] : 0.f;
            }
        }
#pragma unroll 4
        for (int idx = tid; idx < 32 * 128; idx += 256) Ws[idx] = w1[kk * 128 + idx];
        __syncthreads();
#pragma unroll 4
        for (int k = 0; k < 32; ++k) {
            float ra[8];
#pragma unroll
            for (int i = 0; i < 8; ++i) ra[i] = Hc[(ty * 8 + i) * HPAD + k];
            float4 rb0 = *(const float4*)&Ws[k * 128 + tx * 8];
            float4 rb1 = *(const float4*)&Ws[k * 128 + tx * 8 + 4];
            float rb[8] = {rb0.x, rb0.y, rb0.z, rb0.w, rb1.x, rb1.y, rb1.z, rb1.w};
#pragma unroll
            for (int i = 0; i < 8; ++i)
#pragma unroll
                for (int j = 0; j < 8; ++j) acc[i][j] = fmaf(ra[i], rb[j], acc[i][j]);
        }
        __syncthreads();
    }

    {
        float bv[8];
#pragma unroll
        for (int j = 0; j < 8; ++j) bv[j] = b1[tx * 8 + j];
#pragma unroll
        for (int i = 0; i < 8; ++i) {
#pragma unroll
            for (int j = 0; j < 8; ++j) acc[i][j] = fmaxf(acc[i][j] + bv[j], 0.f);
            *(float4*)&Ts[(ty * 8 + i) * EPAD + tx * 8]     = make_float4(acc[i][0], acc[i][1], acc[i][2], acc[i][3]);
            *(float4*)&Ts[(ty * 8 + i) * EPAD + tx * 8 + 4] = make_float4(acc[i][4], acc[i][5], acc[i][6], acc[i][7]);
        }
    }

#pragma unroll
    for (int i = 0; i < 8; ++i)
#pragma unroll
        for (int j = 0; j < 8; ++j) acc[i][j] = 0.f;

    for (int kk = 0; kk < D; kk += 32) {
#pragma unroll 4
        for (int idx = tid; idx < 32 * 128; idx += 256) Ws[idx] = w2[kk * 128 + idx];
        __syncthreads();
#pragma unroll 4
        for (int k = 0; k < 32; ++k) {
            float ra[8];
#pragma unroll
            for (int i = 0; i < 8; ++i) ra[i] = Ts[(ty * 8 + i) * EPAD + kk + k];
            float4 rb0 = *(const float4*)&Ws[k * 128 + tx * 8];
            float4 rb1 = *(const float4*)&Ws[k * 128 + tx * 8 + 4];
            float rb[8] = {rb0.x, rb0.y, rb0.z, rb0.w, rb1.x, rb1.y, rb1.z, rb1.w};
#pragma unroll
            for (int i = 0; i < 8; ++i)
#pragma unroll
                for (int j = 0; j < 8; ++j) acc[i][j] = fmaf(ra[i], rb[j], acc[i][j]);
        }
        __syncthreads();
    }

    {
        float bv[8];
#pragma unroll
        for (int j = 0; j < 8; ++j) bv[j] = b2[tx * 8 + j];
#pragma unroll
        for (int i = 0; i < 8; ++i) {
            int r = ty * 8 + i;
            int n = n0 + r;
            if (n < N_NODES) {
                float o[8];
#pragma unroll
                for (int j = 0; j < 8; ++j) o[j] = acc[i][j] + bv[j];
                *(float4*)&xout[(size_t)n * D + tx * 8]     = make_float4(o[0], o[1], o[2], o[3]);
                *(float4*)&xout[(size_t)n * D + tx * 8 + 4] = make_float4(o[4], o[5], o[6], o[7]);
                float* sbase = xsum + (size_t)bat[r] * D + tx * 8;
                red_add_v4(sbase,     o[0], o[1], o[2], o[3]);
                red_add_v4(sbase + 4, o[4], o[5], o[6], o[7]);
            }
        }
    }
}

// ===========================================================================
// Global MLP (unchanged)
// ===========================================================================
__global__ __launch_bounds__(256, 1)
void global_mlp_kernel(const float* __restrict__ u,
                       const float* __restrict__ xsum,
                       const float* __restrict__ bcnt,
                       const float* __restrict__ w1, const float* __restrict__ b1,
                       const float* __restrict__ w2, const float* __restrict__ b2,
                       float* __restrict__ uout)
{
    extern __shared__ float sm[];
    float* G  = sm;              // [64][256]
    float* Hh = G + 64 * 256;    // [64][EPAD]

    const int tid = threadIdx.x;
    const int tx  = tid & 15;
    const int ty  = tid >> 4;

    for (int idx = tid; idx < 64 * 128; idx += 256) {
        int b = idx >> 7, c = idx & 127;
        G[b * 256 + c]       = u[idx];
        G[b * 256 + 128 + c] = xsum[idx] / fmaxf(bcnt[b], 1.0f);
    }
    __syncthreads();

    float acc[4][8];
#pragma unroll
    for (int i = 0; i < 4; ++i)
#pragma unroll
        for (int j = 0; j < 8; ++j) acc[i][j] = 0.f;

#pragma unroll 4
    for (int k = 0; k < 256; ++k) {
        float ra[4];
#pragma unroll
        for (int i = 0; i < 4; ++i) ra[i] = G[(ty * 4 + i) * 256 + k];
        float4 rb0 = __ldg((const float4*)&w1[k * 128 + tx * 8]);
        float4 rb1 = __ldg((const float4*)&w1[k * 128 + tx * 8 + 4]);
        float rb[8] = {rb0.x, rb0.y, rb0.z, rb0.w, rb1.x, rb1.y, rb1.z, rb1.w};
#pragma unroll
        for (int i = 0; i < 4; ++i)
#pragma unroll
            for (int j = 0; j < 8; ++j) acc[i][j] = fmaf(ra[i], rb[j], acc[i][j]);
    }

    {
        float bv[8];
#pragma unroll
        for (int j = 0; j < 8; ++j) bv[j] = b1[tx * 8 + j];
#pragma unroll
        for (int i = 0; i < 4; ++i) {
#pragma unroll
            for (int j = 0; j < 8; ++j) acc[i][j] = fmaxf(acc[i][j] + bv[j], 0.f);
            *(float4*)&Hh[(ty * 4 + i) * EPAD + tx * 8]     = make_float4(acc[i][0], acc[i][1], acc[i][2], acc[i][3]);
            *(float4*)&Hh[(ty * 4 + i) * EPAD + tx * 8 + 4] = make_float4(acc[i][4], acc[i][5], acc[i][6], acc[i][7]);
        }
    }
    __syncthreads();

#pragma unroll
    for (int i = 0; i < 4; ++i)
#pragma unroll
        for (int j = 0; j < 8; ++j) acc[i][j] = 0.f;

#pragma unroll 4
    for (int k = 0; k < 128; ++k) {
        float ra[4];
#pragma unroll
        for (int i = 0; i < 4; ++i) ra[i] = Hh[(ty * 4 + i) * EPAD + k];
        float4 rb0 = __ldg((const float4*)&w2[k * 128 + tx * 8]);
        float4 rb1 = __ldg((const float4*)&w2[k * 128 + tx * 8 + 4]);
        float rb[8] = {rb0.x, rb0.y, rb0.z, rb0.w, rb1.x, rb1.y, rb1.z, rb1.w};
#pragma unroll
        for (int i = 0; i < 4; ++i)
#pragma unroll
            for (int j = 0; j < 8; ++j) acc[i][j] = fmaf(ra[i], rb[j], acc[i][j]);
    }

    {
        float bv[8];
#pragma unroll
        for (int j = 0; j < 8; ++j) bv[j] = b2[tx * 8 + j];
#pragma unroll
        for (int i = 0; i < 4; ++i) {
            int b = ty * 4 + i;
            *(float4*)&uout[b * D + tx * 8]     = make_float4(acc[i][0] + bv[0], acc[i][1] + bv[1],
                                                              acc[i][2] + bv[2], acc[i][3] + bv[3]);
            *(float4*)&uout[b * D + tx * 8 + 4] = make_float4(acc[i][4] + bv[4], acc[i][5] + bv[5],
                                                              acc[i][6] + bv[6], acc[i][7] + bv[7]);
        }
    }
}

// ===========================================================================
// Host side
// ===========================================================================
static const int NODE_SMEM = (128 * HPAD + 32 * 128 + 128 * EPAD + 128) * 4 + 128 * 4;
static const int GLOB_SMEM = (64 * 256 + 64 * EPAD) * 4;

extern "C" void kernel_launch(void* const* d_in, const int* in_sizes, int n_in,
                              void* d_out, int out_size) {
    const float* x0    = (const float*)d_in[0];
    const int*   ei    = (const int*)d_in[1];      // int32 (JAX x64 disabled)
    const float* u0    = (const float*)d_in[2];
    const int*   batch = (const int*)d_in[3];      // int32
    const float* n1w1 = (const float*)d_in[4];
    const float* n1b1 = (const float*)d_in[5];
    const float* n1w2 = (const float*)d_in[6];
    const float* n1b2 = (const float*)d_in[7];
    const float* n2w1 = (const float*)d_in[8];
    const float* n2b1 = (const float*)d_in[9];
    const float* n2w2 = (const float*)d_in[10];
    const float* n2b2 = (const float*)d_in[11];
    const float* gw1  = (const float*)d_in[12];
    const float* gb1  = (const float*)d_in[13];
    const float* gw2  = (const float*)d_in[14];
    const float* gb2  = (const float*)d_in[15];
    float* out = (float*)d_out;

    float *px, *pu, *pagg, *pcnt, *pxsum, *pbcnt;
    unsigned char* pwt;
    cudaGetSymbolAddress((void**)&px,    g_x);
    cudaGetSymbolAddress((void**)&pu,    g_u);
    cudaGetSymbolAddress((void**)&pagg,  g_agg);
    cudaGetSymbolAddress((void**)&pcnt,  g_cnt);
    cudaGetSymbolAddress((void**)&pxsum, g_xsum);
    cudaGetSymbolAddress((void**)&pbcnt, g_bcnt);
    cudaGetSymbolAddress((void**)&pwt,   g_wt);
    float* xbuf[2] = {px, px + (size_t)N_NODES * D};
    float* ubuf[2] = {pu, pu + (size_t)NB * D};

    cudaFuncSetAttribute(edge_mlp_mma_kernel, cudaFuncAttributeMaxDynamicSharedMemorySize, EDGE_SMEM);
    cudaFuncSetAttribute(node_mlp_kernel,     cudaFuncAttributeMaxDynamicSharedMemorySize, NODE_SMEM);
    cudaFuncSetAttribute(global_mlp_kernel,   cudaFuncAttributeMaxDynamicSharedMemorySize, GLOB_SMEM);

    // one-time per launch: counts + weight tiles
    cudaMemsetAsync(pcnt,  0, N_NODES * sizeof(float));
    cudaMemsetAsync(pbcnt, 0, NB * sizeof(float));
    count_edges_kernel<<<(N_EDGES + 255) / 256, 256>>>(ei, pcnt);
    count_batch_kernel<<<(N_NODES + 255) / 256, 256>>>(batch, pbcnt);
    prep_weights_kernel<<<2 * NLAYERS, 256>>>(n1w1, n1w2);

    const float* xc = x0;
    const float* uc = u0;
    for (int l = 0; l < NLAYERS; ++l) {
        cudaMemsetAsync(pagg,  0, (size_t)N_NODES * D * sizeof(float));
        cudaMemsetAsync(pxsum, 0, (size_t)NB * D * sizeof(float));

        const unsigned char* w1hi = pwt + (size_t)(l * 4 + 0) * WTILE_BYTES;
        const unsigned char* w1lo = pwt + (size_t)(l * 4 + 1) * WTILE_BYTES;
        const unsigned char* w2hi = pwt + (size_t)(l * 4 + 2) * WTILE_BYTES;
        const unsigned char* w2lo = pwt + (size_t)(l * 4 + 3) * WTILE_BYTES;

        edge_mlp_mma_kernel<<<(N_EDGES + 127) / 128, ETHREADS, EDGE_SMEM>>>(
            xc, ei, w1hi, w1lo, w2hi, w2lo,
            n1b1 + (size_t)l * D, n1b2 + (size_t)l * D, pagg);

        float* xn = (l == NLAYERS - 1) ? out : xbuf[l & 1];
        node_mlp_kernel<<<(N_NODES + 127) / 128, 256, NODE_SMEM>>>(
            xc, pagg, pcnt, uc, batch,
            n2w1 + (size_t)l * 384 * D, n2b1 + (size_t)l * D,
            n2w2 + (size_t)l * D * D,   n2b2 + (size_t)l * D,
            xn, pxsum);

        float* un = (l == NLAYERS - 1) ? out + (size_t)N_NODES * D : ubuf[l & 1];
        global_mlp_kernel<<<1, 256, GLOB_SMEM>>>(
            uc, pxsum, pbcnt,
            gw1 + (size_t)l * 256 * D, gb1 + (size_t)l * D,
            gw2 + (size_t)l * D * D,   gb2 + (size_t)l * D,
            un);

        xc = xn;
        uc = un;
    }
}

// round 11
// speedup vs baseline: 1.2473x; 1.0786x over previous
#include <cuda_runtime.h>
#include <cuda_bf16.h>
#include <cstdint>

#define N_NODES 50000
#define N_EDGES 600000
#define NB      64
#define D       128      // F == H == U
#define NLAYERS 4

#define EPAD 132   // padded row stride for 128-wide smem tiles (node/global)
#define HPAD 36    // padded row stride for 32-wide K chunks (node)

#define LDA 136                      // bf16 row stride for mma tiles (272B, 16B-aligned)
#define WTILE_BYTES (128 * LDA * 2)  // 34816 bytes per 128x128 bf16 tile
#define NTILES ((N_EDGES + 127) / 128)   // 4688 edge tiles

// ===========================================================================
// Scratch (no allocations allowed -> __device__ globals)
// ===========================================================================
__device__ float g_x[2][N_NODES * D];
__device__ float g_u[2][NB * D];
__device__ float g_agg[N_NODES * D];
__device__ float g_cnt[N_NODES];
__device__ float g_xsum[NB * D];
__device__ float g_bcnt[NB];
// transposed/split bf16 weight tiles [n][k], padded LDA: [layer][w1,w2][hi,lo]
__device__ __align__(16) unsigned char g_wt[16 * WTILE_BYTES];

__device__ __forceinline__ void red_add_v4(float* addr, float a, float b, float c, float d) {
    asm volatile("red.global.add.v4.f32 [%0], {%1,%2,%3,%4};"
                 :: "l"(addr), "f"(a), "f"(b), "f"(c), "f"(d) : "memory");
}
__device__ __forceinline__ void red_add_v2(float* addr, float a, float b) {
    asm volatile("red.global.add.v2.f32 [%0], {%1,%2};"
                 :: "l"(addr), "f"(a), "f"(b) : "memory");
}

__device__ __forceinline__ uint32_t smem_u32(const void* p) {
    uint32_t a;
    asm("{ .reg .u64 t; cvta.to.shared.u64 t, %1; cvt.u32.u64 %0, t; }" : "=r"(a) : "l"(p));
    return a;
}

__device__ __forceinline__ void ldsm4(uint32_t addr, uint32_t r[4]) {
    asm volatile("ldmatrix.sync.aligned.m8n8.x4.shared.b16 {%0,%1,%2,%3}, [%4];"
                 : "=r"(r[0]), "=r"(r[1]), "=r"(r[2]), "=r"(r[3]) : "r"(addr));
}

__device__ __forceinline__ void mma16816(float d[4], const uint32_t a[4],
                                         uint32_t b0, uint32_t b1) {
    asm volatile(
        "mma.sync.aligned.m16n8k16.row.col.f32.bf16.bf16.f32 "
        "{%0,%1,%2,%3}, {%4,%5,%6,%7}, {%8,%9}, {%0,%1,%2,%3};"
        : "+f"(d[0]), "+f"(d[1]), "+f"(d[2]), "+f"(d[3])
        : "r"(a[0]), "r"(a[1]), "r"(a[2]), "r"(a[3]), "r"(b0), "r"(b1));
}

__device__ __forceinline__ uint32_t pack_bf16_hi(float f0, float f1) {
    return ((uint32_t)__bfloat16_as_ushort(__float2bfloat16_rn(f1)) << 16)
         |  (uint32_t)__bfloat16_as_ushort(__float2bfloat16_rn(f0));
}

// ===========================================================================
// One-time kernels
// ===========================================================================
__global__ void count_edges_kernel(const int* __restrict__ ei, float* __restrict__ cnt) {
    int e = blockIdx.x * 256 + threadIdx.x;
    if (e < N_EDGES) atomicAdd(&cnt[ei[N_EDGES + e]], 1.0f);
}
__global__ void count_batch_kernel(const int* __restrict__ batch, float* __restrict__ bcnt) {
    int n = blockIdx.x * 256 + threadIdx.x;
    if (n < N_NODES) atomicAdd(&bcnt[batch[n]], 1.0f);
}

// Transpose+split W (row-major [K=128, N=128]) into bf16 hi/lo tiles [n][k], LDA pad.
__global__ void prep_weights_kernel(const float* __restrict__ n1w1,
                                    const float* __restrict__ n1w2) {
    int b = blockIdx.x;                 // 0..7: (layer, w1/w2)
    int l = b >> 1, which = b & 1;
    const float* w = (which ? n1w2 : n1w1) + (size_t)l * D * D;
    unsigned char* thi = g_wt + ((size_t)b * 2 + 0) * WTILE_BYTES;
    unsigned char* tlo = g_wt + ((size_t)b * 2 + 1) * WTILE_BYTES;
    for (int idx = threadIdx.x; idx < 128 * 32; idx += 256) {
        int n = idx >> 5, kq = (idx & 31) << 2;
        unsigned short hh[4], ll[4];
#pragma unroll
        for (int q = 0; q < 4; ++q) {
            float f = w[(kq + q) * D + n];
            __nv_bfloat16 h = __float2bfloat16_rn(f);
            float r = f - __bfloat162float(h);
            hh[q] = __bfloat16_as_ushort(h);
            ll[q] = __bfloat16_as_ushort(__float2bfloat16_rn(r));
        }
        uint32_t o = (uint32_t)(n * LDA + kq) * 2;
        *(uint2*)(thi + o) = make_uint2(((uint32_t)hh[1] << 16) | hh[0],
                                        ((uint32_t)hh[3] << 16) | hh[2]);
        *(uint2*)(tlo + o) = make_uint2(((uint32_t)ll[1] << 16) | ll[0],
                                        ((uint32_t)ll[3] << 16) | ll[2]);
    }
}

// ===========================================================================
// Edge MLP via mma.sync (split-bf16, 3-term), persistent CTAs,
// all four weight tiles resident in smem, grid-stride over edge tiles.
// ===========================================================================
#define SM_COLS   0                               // int[128]
#define SM_B1     512                             // float[128]
#define SM_B2     1024                            // float[128]
#define A_HI_OFF  2048
#define A_LO_OFF  (A_HI_OFF  + WTILE_BYTES)
#define W1_HI_OFF (A_LO_OFF  + WTILE_BYTES)
#define W1_LO_OFF (W1_HI_OFF + WTILE_BYTES)
#define W2_HI_OFF (W1_LO_OFF + WTILE_BYTES)
#define W2_LO_OFF (W2_HI_OFF + WTILE_BYTES)
static const int EDGE_SMEM = W2_LO_OFF + WTILE_BYTES;   // 210944
#define ETHREADS 512

// One split GEMM pass over K=128: D += Ahi@Whi + Ahi@Wlo + Alo@Whi.
// Warp tile 32x32: d[2 m16][4 n8][4].
__device__ __forceinline__ void gemm_split32(uint32_t aHi, uint32_t aLo,
                                             uint32_t wHi, uint32_t wLo,
                                             int mrow, int ncol, int lane,
                                             float d[2][4][4]) {
    const int a_row  = lane & 15;
    const int a_koff = (lane >> 4) << 3;
    const int b_nrow = ((lane >> 4) << 3) + (lane & 7);
    const int b_koff = ((lane >> 3) & 1) << 3;
#pragma unroll
    for (int ks = 0; ks < 8; ++ks) {
        const int kb = ks * 16;
        uint32_t ah[2][4], al[2][4];
#pragma unroll
        for (int mt = 0; mt < 2; ++mt) {
            uint32_t off = (uint32_t)(((mrow + mt * 16 + a_row) * LDA + kb + a_koff) * 2);
            ldsm4(aHi + off, ah[mt]);
            ldsm4(aLo + off, al[mt]);
        }
#pragma unroll
        for (int p = 0; p < 2; ++p) {   // pairs of n8 tiles
            uint32_t off = (uint32_t)(((ncol + p * 16 + b_nrow) * LDA + kb + b_koff) * 2);
            uint32_t bh[4], bl[4];
            ldsm4(wHi + off, bh);
            ldsm4(wLo + off, bl);
#pragma unroll
            for (int h = 0; h < 2; ++h) {
                const int nt = p * 2 + h;
#pragma unroll
                for (int mt = 0; mt < 2; ++mt) {
                    mma16816(d[mt][nt], ah[mt], bh[2 * h], bh[2 * h + 1]);
                    mma16816(d[mt][nt], ah[mt], bl[2 * h], bl[2 * h + 1]);
                    mma16816(d[mt][nt], al[mt], bh[2 * h], bh[2 * h + 1]);
                }
            }
        }
    }
}

__global__ __launch_bounds__(ETHREADS, 1)
void edge_mlp_mma_kernel(const float* __restrict__ x, const int* __restrict__ ei,
                         const unsigned char* __restrict__ w1hi, const unsigned char* __restrict__ w1lo,
                         const unsigned char* __restrict__ w2hi, const unsigned char* __restrict__ w2lo,
                         const float* __restrict__ b1, const float* __restrict__ b2,
                         float* __restrict__ agg)
{
    extern __shared__ char smc[];
    int*   colS = (int*)(smc + SM_COLS);
    float* b1s  = (float*)(smc + SM_B1);
    float* b2s  = (float*)(smc + SM_B2);

    const int tid  = threadIdx.x;
    const int warp = tid >> 5;
    const int lane = tid & 31;

    const uint32_t sbase = smem_u32(smc);
    const uint32_t aHi  = sbase + A_HI_OFF,  aLo  = sbase + A_LO_OFF;
    const uint32_t w1Hi = sbase + W1_HI_OFF, w1Lo = sbase + W1_LO_OFF;
    const uint32_t w2Hi = sbase + W2_HI_OFF, w2Lo = sbase + W2_LO_OFF;

    // ---- load ALL weight tiles + biases once per CTA ----
    {
        uint4* d1h = (uint4*)(smc + W1_HI_OFF);
        uint4* d1l = (uint4*)(smc + W1_LO_OFF);
        uint4* d2h = (uint4*)(smc + W2_HI_OFF);
        uint4* d2l = (uint4*)(smc + W2_LO_OFF);
        const uint4* s1h = (const uint4*)w1hi;
        const uint4* s1l = (const uint4*)w1lo;
        const uint4* s2h = (const uint4*)w2hi;
        const uint4* s2l = (const uint4*)w2lo;
        for (int i = tid; i < WTILE_BYTES / 16; i += ETHREADS) {
            d1h[i] = s1h[i]; d1l[i] = s1l[i];
            d2h[i] = s2h[i]; d2l[i] = s2l[i];
        }
        if (tid < 128) { b1s[tid] = b1[tid]; b2s[tid] = b2[tid]; }
    }

    const int mrow = (warp >> 2) * 32;   // 4 warps down M
    const int ncol = (warp & 3) * 32;    // 4 warps across N
    const int crow = lane >> 2;
    const int ccol = (lane & 3) * 2;

    __syncthreads();

    // ---- grid-stride over edge tiles ----
    for (int t = blockIdx.x; t < NTILES; t += gridDim.x) {
        const int e0 = t * 128;

        // gather 128 edge-source rows, split to bf16 hi/lo
        for (int r = warp; r < 128; r += 16) {
            int e = e0 + r;
            float4 v = make_float4(0.f, 0.f, 0.f, 0.f);
            if (e < N_EDGES) {
                if (lane == 0) colS[r] = ei[N_EDGES + e];
                v = *((const float4*)(x + (size_t)ei[e] * D) + lane);
            } else if (lane == 0) colS[r] = -1;
            float vv[4] = {v.x, v.y, v.z, v.w};
            unsigned short h[4], lo[4];
#pragma unroll
            for (int q = 0; q < 4; ++q) {
                __nv_bfloat16 hh = __float2bfloat16_rn(vv[q]);
                float rr = vv[q] - __bfloat162float(hh);
                h[q]  = __bfloat16_as_ushort(hh);
                lo[q] = __bfloat16_as_ushort(__float2bfloat16_rn(rr));
            }
            uint32_t o = (uint32_t)(r * LDA + lane * 4) * 2;
            *(uint2*)(smc + A_HI_OFF + o) = make_uint2(((uint32_t)h[1] << 16) | h[0],
                                                       ((uint32_t)h[3] << 16) | h[2]);
            *(uint2*)(smc + A_LO_OFF + o) = make_uint2(((uint32_t)lo[1] << 16) | lo[0],
                                                       ((uint32_t)lo[3] << 16) | lo[2]);
        }
        __syncthreads();

        float d[2][4][4];
#pragma unroll
        for (int mt = 0; mt < 2; ++mt)
#pragma unroll
            for (int nt = 0; nt < 4; ++nt)
#pragma unroll
                for (int q = 0; q < 4; ++q) d[mt][nt][q] = 0.f;

        // GEMM1: D1 = A @ W1 (3-term split)
        gemm_split32(aHi, aLo, w1Hi, w1Lo, mrow, ncol, lane, d);

        __syncthreads();   // all warps done reading A before T overwrites it

        // Epilogue 1: bias+relu, re-split, T -> A smem buffers
#pragma unroll
        for (int mt = 0; mt < 2; ++mt) {
#pragma unroll
            for (int nt = 0; nt < 4; ++nt) {
                const int row = mrow + mt * 16 + crow;
                const int col = ncol + nt * 8 + ccol;
                float f0 = fmaxf(d[mt][nt][0] + b1s[col],     0.f);
                float f1 = fmaxf(d[mt][nt][1] + b1s[col + 1], 0.f);
                float f2 = fmaxf(d[mt][nt][2] + b1s[col],     0.f);
                float f3 = fmaxf(d[mt][nt][3] + b1s[col + 1], 0.f);
                uint32_t o0 = (uint32_t)(row * LDA + col) * 2;
                uint32_t o1 = (uint32_t)((row + 8) * LDA + col) * 2;
                *(uint32_t*)(smc + A_HI_OFF + o0) = pack_bf16_hi(f0, f1);
                *(uint32_t*)(smc + A_HI_OFF + o1) = pack_bf16_hi(f2, f3);
                float r0 = f0 - __bfloat162float(__float2bfloat16_rn(f0));
                float r1 = f1 - __bfloat162float(__float2bfloat16_rn(f1));
                float r2 = f2 - __bfloat162float(__float2bfloat16_rn(f2));
                float r3 = f3 - __bfloat162float(__float2bfloat16_rn(f3));
                *(uint32_t*)(smc + A_LO_OFF + o0) = pack_bf16_hi(r0, r1);
                *(uint32_t*)(smc + A_LO_OFF + o1) = pack_bf16_hi(r2, r3);
            }
        }
        __syncthreads();   // T visible to all warps

#pragma unroll
        for (int mt = 0; mt < 2; ++mt)
#pragma unroll
            for (int nt = 0; nt < 4; ++nt)
#pragma unroll
                for (int q = 0; q < 4; ++q) d[mt][nt][q] = 0.f;

        // GEMM2: D2 = T @ W2
        gemm_split32(aHi, aLo, w2Hi, w2Lo, mrow, ncol, lane, d);

        __syncthreads();   // all warps done reading A before next tile's gather

        // Epilogue 2: bias + red.v2 scatter into agg[col] (registers only)
#pragma unroll
        for (int mt = 0; mt < 2; ++mt) {
            const int row0 = mrow + mt * 16 + crow;
            const int c0 = colS[row0];
            const int c1 = colS[row0 + 8];
#pragma unroll
            for (int nt = 0; nt < 4; ++nt) {
                const int col = ncol + nt * 8 + ccol;
                if (c0 >= 0)
                    red_add_v2(agg + (size_t)c0 * D + col,
                               d[mt][nt][0] + b2s[col], d[mt][nt][1] + b2s[col + 1]);
                if (c1 >= 0)
                    red_add_v2(agg + (size_t)c1 * D + col,
                               d[mt][nt][2] + b2s[col], d[mt][nt][3] + b2s[col + 1]);
            }
        }
        // NOTE: colS is re-written next iteration only after the gather sync,
        // and scatter reads it before that sync -> safe.
    }
}

// ===========================================================================
// Node MLP (FFMA; occupancy 2)
// ===========================================================================
__global__ __launch_bounds__(256, 2)
void node_mlp_kernel(const float* __restrict__ x,
                     const float* __restrict__ agg,
                     const float* __restrict__ cnt,
                     const float* __restrict__ u,
                     const int* __restrict__ batch,
                     const float* __restrict__ w1, const float* __restrict__ b1,
                     const float* __restrict__ w2, const float* __restrict__ b2,
                     float* __restrict__ xout,
                     float* __restrict__ xsum)
{
    extern __shared__ float sm[];
    float* Hc  = sm;                       // [128][HPAD]
    float* Ws  = Hc + 128 * HPAD;          // [32][128]
    float* Ts  = Ws + 32 * 128;            // [128][EPAD]
    float* rcp = Ts + 128 * EPAD;          // [128]
    int*   bat = (int*)(rcp + 128);        // [128]

    const int tid = threadIdx.x;
    const int tx  = tid & 15;
    const int ty  = tid >> 4;
    const int n0  = blockIdx.x * 128;

    if (tid < 128) {
        int n = n0 + tid;
        if (n < N_NODES) {
            rcp[tid] = 1.0f / fmaxf(cnt[n], 1.0f);
            bat[tid] = batch[n];
        } else {
            rcp[tid] = 0.f;
            bat[tid] = 0;
        }
    }
    __syncthreads();

    float acc[8][8];
#pragma unroll
    for (int i = 0; i < 8; ++i)
#pragma unroll
        for (int j = 0; j < 8; ++j) acc[i][j] = 0.f;

    for (int kk = 0; kk < 384; kk += 32) {
        if (kk < 128) {
            for (int idx = tid; idx < 128 * 32; idx += 256) {
                int r = idx >> 5, k = idx & 31, n = n0 + r;
                Hc[r * HPAD + k] = (n < N_NODES) ? x[(size_t)n * D + kk + k] : 0.f;
            }
        } else if (kk < 256) {
            for (int idx = tid; idx < 128 * 32; idx += 256) {
                int r = idx >> 5, k = idx & 31, n = n0 + r;
                Hc[r * HPAD + k] = (n < N_NODES) ? agg[(size_t)n * D + (kk - 128) + k] * rcp[r] : 0.f;
            }
        } else {
            for (int idx = tid; idx < 128 * 32; idx += 256) {
                int r = idx >> 5, k = idx & 31, n = n0 + r;
                Hc[r * HPAD + k] = (n < N_NODES) ? u[bat[r] * D + (kk - 256) + k] : 0.f;
            }
        }
#pragma unroll 4
        for (int idx = tid; idx < 32 * 128; idx += 256) Ws[idx] = w1[kk * 128 + idx];
        __syncthreads();
#pragma unroll 4
        for (int k = 0; k < 32; ++k) {
            float ra[8];
#pragma unroll
            for (int i = 0; i < 8; ++i) ra[i] = Hc[(ty * 8 + i) * HPAD + k];
            float4 rb0 = *(const float4*)&Ws[k * 128 + tx * 8];
            float4 rb1 = *(const float4*)&Ws[k * 128 + tx * 8 + 4];
            float rb[8] = {rb0.x, rb0.y, rb0.z, rb0.w, rb1.x, rb1.y, rb1.z, rb1.w};
#pragma unroll
            for (int i = 0; i < 8; ++i)
#pragma unroll
                for (int j = 0; j < 8; ++j) acc[i][j] = fmaf(ra[i], rb[j], acc[i][j]);
        }
        __syncthreads();
    }

    {
        float bv[8];
#pragma unroll
        for (int j = 0; j < 8; ++j) bv[j] = b1[tx * 8 + j];
#pragma unroll
        for (int i = 0; i < 8; ++i) {
#pragma unroll
            for (int j = 0; j < 8; ++j) acc[i][j] = fmaxf(acc[i][j] + bv[j], 0.f);
            *(float4*)&Ts[(ty * 8 + i) * EPAD + tx * 8]     = make_float4(acc[i][0], acc[i][1], acc[i][2], acc[i][3]);
            *(float4*)&Ts[(ty * 8 + i) * EPAD + tx * 8 + 4] = make_float4(acc[i][4], acc[i][5], acc[i][6], acc[i][7]);
        }
    }

#pragma unroll
    for (int i = 0; i < 8; ++i)
#pragma unroll
        for (int j = 0; j < 8; ++j) acc[i][j] = 0.f;

    for (int kk = 0; kk < D; kk += 32) {
#pragma unroll 4
        for (int idx = tid; idx < 32 * 128; idx += 256) Ws[idx] = w2[kk * 128 + idx];
        __syncthreads();
#pragma unroll 4
        for (int k = 0; k < 32; ++k) {
            float ra[8];
#pragma unroll
            for (int i = 0; i < 8; ++i) ra[i] = Ts[(ty * 8 + i) * EPAD + kk + k];
            float4 rb0 = *(const float4*)&Ws[k * 128 + tx * 8];
            float4 rb1 = *(const float4*)&Ws[k * 128 + tx * 8 + 4];
            float rb[8] = {rb0.x, rb0.y, rb0.z, rb0.w, rb1.x, rb1.y, rb1.z, rb1.w};
#pragma unroll
            for (int i = 0; i < 8; ++i)
#pragma unroll
                for (int j = 0; j < 8; ++j) acc[i][j] = fmaf(ra[i], rb[j], acc[i][j]);
        }
        __syncthreads();
    }

    {
        float bv[8];
#pragma unroll
        for (int j = 0; j < 8; ++j) bv[j] = b2[tx * 8 + j];
#pragma unroll
        for (int i = 0; i < 8; ++i) {
            int r = ty * 8 + i;
            int n = n0 + r;
            if (n < N_NODES) {
                float o[8];
#pragma unroll
                for (int j = 0; j < 8; ++j) o[j] = acc[i][j] + bv[j];
                *(float4*)&xout[(size_t)n * D + tx * 8]     = make_float4(o[0], o[1], o[2], o[3]);
                *(float4*)&xout[(size_t)n * D + tx * 8 + 4] = make_float4(o[4], o[5], o[6], o[7]);
                float* sbase = xsum + (size_t)bat[r] * D + tx * 8;
                red_add_v4(sbase,     o[0], o[1], o[2], o[3]);
                red_add_v4(sbase + 4, o[4], o[5], o[6], o[7]);
            }
        }
    }
}

// ===========================================================================
// Global MLP (unchanged)
// ===========================================================================
__global__ __launch_bounds__(256, 1)
void global_mlp_kernel(const float* __restrict__ u,
                       const float* __restrict__ xsum,
                       const float* __restrict__ bcnt,
                       const float* __restrict__ w1, const float* __restrict__ b1,
                       const float* __restrict__ w2, const float* __restrict__ b2,
                       float* __restrict__ uout)
{
    extern __shared__ float sm[];
    float* G  = sm;              // [64][256]
    float* Hh = G + 64 * 256;    // [64][EPAD]

    const int tid = threadIdx.x;
    const int tx  = tid & 15;
    const int ty  = tid >> 4;

    for (int idx = tid; idx < 64 * 128; idx += 256) {
        int b = idx >> 7, c = idx & 127;
        G[b * 256 + c]       = u[idx];
        G[b * 256 + 128 + c] = xsum[idx] / fmaxf(bcnt[b], 1.0f);
    }
    __syncthreads();

    float acc[4][8];
#pragma unroll
    for (int i = 0; i < 4; ++i)
#pragma unroll
        for (int j = 0; j < 8; ++j) acc[i][j] = 0.f;

#pragma unroll 4
    for (int k = 0; k < 256; ++k) {
        float ra[4];
#pragma unroll
        for (int i = 0; i < 4; ++i) ra[i] = G[(ty * 4 + i) * 256 + k];
        float4 rb0 = __ldg((const float4*)&w1[k * 128 + tx * 8]);
        float4 rb1 = __ldg((const float4*)&w1[k * 128 + tx * 8 + 4]);
        float rb[8] = {rb0.x, rb0.y, rb0.z, rb0.w, rb1.x, rb1.y, rb1.z, rb1.w};
#pragma unroll
        for (int i = 0; i < 4; ++i)
#pragma unroll
            for (int j = 0; j < 8; ++j) acc[i][j] = fmaf(ra[i], rb[j], acc[i][j]);
    }

    {
        float bv[8];
#pragma unroll
        for (int j = 0; j < 8; ++j) bv[j] = b1[tx * 8 + j];
#pragma unroll
        for (int i = 0; i < 4; ++i) {
#pragma unroll
            for (int j = 0; j < 8; ++j) acc[i][j] = fmaxf(acc[i][j] + bv[j], 0.f);
            *(float4*)&Hh[(ty * 4 + i) * EPAD + tx * 8]     = make_float4(acc[i][0], acc[i][1], acc[i][2], acc[i][3]);
            *(float4*)&Hh[(ty * 4 + i) * EPAD + tx * 8 + 4] = make_float4(acc[i][4], acc[i][5], acc[i][6], acc[i][7]);
        }
    }
    __syncthreads();

#pragma unroll
    for (int i = 0; i < 4; ++i)
#pragma unroll
        for (int j = 0; j < 8; ++j) acc[i][j] = 0.f;

#pragma unroll 4
    for (int k = 0; k < 128; ++k) {
        float ra[4];
#pragma unroll
        for (int i = 0; i < 4; ++i) ra[i] = Hh[(ty * 4 + i) * EPAD + k];
        float4 rb0 = __ldg((const float4*)&w2[k * 128 + tx * 8]);
        float4 rb1 = __ldg((const float4*)&w2[k * 128 + tx * 8 + 4]);
        float rb[8] = {rb0.x, rb0.y, rb0.z, rb0.w, rb1.x, rb1.y, rb1.z, rb1.w};
#pragma unroll
        for (int i = 0; i < 4; ++i)
#pragma unroll
            for (int j = 0; j < 8; ++j) acc[i][j] = fmaf(ra[i], rb[j], acc[i][j]);
    }

    {
        float bv[8];
#pragma unroll
        for (int j = 0; j < 8; ++j) bv[j] = b2[tx * 8 + j];
#pragma unroll
        for (int i = 0; i < 4; ++i) {
            int b = ty * 4 + i;
            *(float4*)&uout[b * D + tx * 8]     = make_float4(acc[i][0] + bv[0], acc[i][1] + bv[1],
                                                              acc[i][2] + bv[2], acc[i][3] + bv[3]);
            *(float4*)&uout[b * D + tx * 8 + 4] = make_float4(acc[i][4] + bv[4], acc[i][5] + bv[5],
                                                              acc[i][6] + bv[6], acc[i][7] + bv[7]);
        }
    }
}

// ===========================================================================
// Host side
// ===========================================================================
static const int NODE_SMEM = (128 * HPAD + 32 * 128 + 128 * EPAD + 128) * 4 + 128 * 4;
static const int GLOB_SMEM = (64 * 256 + 64 * EPAD) * 4;
#define EDGE_GRID 148

extern "C" void kernel_launch(void* const* d_in, const int* in_sizes, int n_in,
                              void* d_out, int out_size) {
    const float* x0    = (const float*)d_in[0];
    const int*   ei    = (const int*)d_in[1];      // int32 (JAX x64 disabled)
    const float* u0    = (const float*)d_in[2];
    const int*   batch = (const int*)d_in[3];      // int32
    const float* n1w1 = (const float*)d_in[4];
    const float* n1b1 = (const float*)d_in[5];
    const float* n1w2 = (const float*)d_in[6];
    const float* n1b2 = (const float*)d_in[7];
    const float* n2w1 = (const float*)d_in[8];
    const float* n2b1 = (const float*)d_in[9];
    const float* n2w2 = (const float*)d_in[10];
    const float* n2b2 = (const float*)d_in[11];
    const float* gw1  = (const float*)d_in[12];
    const float* gb1  = (const float*)d_in[13];
    const float* gw2  = (const float*)d_in[14];
    const float* gb2  = (const float*)d_in[15];
    float* out = (float*)d_out;

    float *px, *pu, *pagg, *pcnt, *pxsum, *pbcnt;
    unsigned char* pwt;
    cudaGetSymbolAddress((void**)&px,    g_x);
    cudaGetSymbolAddress((void**)&pu,    g_u);
    cudaGetSymbolAddress((void**)&pagg,  g_agg);
    cudaGetSymbolAddress((void**)&pcnt,  g_cnt);
    cudaGetSymbolAddress((void**)&pxsum, g_xsum);
    cudaGetSymbolAddress((void**)&pbcnt, g_bcnt);
    cudaGetSymbolAddress((void**)&pwt,   g_wt);
    float* xbuf[2] = {px, px + (size_t)N_NODES * D};
    float* ubuf[2] = {pu, pu + (size_t)NB * D};

    cudaFuncSetAttribute(edge_mlp_mma_kernel, cudaFuncAttributeMaxDynamicSharedMemorySize, EDGE_SMEM);
    cudaFuncSetAttribute(node_mlp_kernel,     cudaFuncAttributeMaxDynamicSharedMemorySize, NODE_SMEM);
    cudaFuncSetAttribute(global_mlp_kernel,   cudaFuncAttributeMaxDynamicSharedMemorySize, GLOB_SMEM);

    // one-time per launch: counts + weight tiles
    cudaMemsetAsync(pcnt,  0, N_NODES * sizeof(float));
    cudaMemsetAsync(pbcnt, 0, NB * sizeof(float));
    count_edges_kernel<<<(N_EDGES + 255) / 256, 256>>>(ei, pcnt);
    count_batch_kernel<<<(N_NODES + 255) / 256, 256>>>(batch, pbcnt);
    prep_weights_kernel<<<2 * NLAYERS, 256>>>(n1w1, n1w2);

    const float* xc = x0;
    const float* uc = u0;
    for (int l = 0; l < NLAYERS; ++l) {
        cudaMemsetAsync(pagg,  0, (size_t)N_NODES * D * sizeof(float));
        cudaMemsetAsync(pxsum, 0, (size_t)NB * D * sizeof(float));

        const unsigned char* w1hi = pwt + (size_t)(l * 4 + 0) * WTILE_BYTES;
        const unsigned char* w1lo = pwt + (size_t)(l * 4 + 1) * WTILE_BYTES;
        const unsigned char* w2hi = pwt + (size_t)(l * 4 + 2) * WTILE_BYTES;
        const unsigned char* w2lo = pwt + (size_t)(l * 4 + 3) * WTILE_BYTES;

        edge_mlp_mma_kernel<<<EDGE_GRID, ETHREADS, EDGE_SMEM>>>(
            xc, ei, w1hi, w1lo, w2hi, w2lo,
            n1b1 + (size_t)l * D, n1b2 + (size_t)l * D, pagg);

        float* xn = (l == NLAYERS - 1) ? out : xbuf[l & 1];
        node_mlp_kernel<<<(N_NODES + 127) / 128, 256, NODE_SMEM>>>(
            xc, pagg, pcnt, uc, batch,
            n2w1 + (size_t)l * 384 * D, n2b1 + (size_t)l * D,
            n2w2 + (size_t)l * D * D,   n2b2 + (size_t)l * D,
            xn, pxsum);

        float* un = (l == NLAYERS - 1) ? out + (size_t)N_NODES * D : ubuf[l & 1];
        global_mlp_kernel<<<1, 256, GLOB_SMEM>>>(
            uc, pxsum, pbcnt,
            gw1 + (size_t)l * 256 * D, gb1 + (size_t)l * D,
            gw2 + (size_t)l * D * D,   gb2 + (size_t)l * D,
            un);

        xc = xn;
        uc = un;
    }
}